// round 2
// baseline (speedup 1.0000x reference)
#include <cuda_runtime.h>
#include <math.h>

// Problem constants (fixed by dataset)
#define PDIM  100000
#define NANCH 1000
#define BPRIV 256

constexpr int GSPLIT   = 10;   // K-splits for G = A A^T     (chunk 10000)
constexpr int CSPLIT   = 25;   // K-splits for C = priv A^T  (chunk 4000)
constexpr int VSPLIT   = 8;    // K-splits for CG matvec     (chunk 128)
constexpr int CG_ITERS = 8;

// ---- static device scratch (no allocations allowed) ----
__device__ float g_Gp[GSPLIT * NANCH * NANCH];   // 40 MB
__device__ float g_G [NANCH * NANCH];
__device__ float g_Cp[CSPLIT * BPRIV * NANCH];   // 25.6 MB
__device__ float g_C [BPRIV * NANCH];
__device__ float g_Y [BPRIV * NANCH];
__device__ float g_Rr[BPRIV * NANCH];
__device__ float g_Pd[BPRIV * NANCH];
__device__ float g_V [BPRIV * NANCH];
__device__ float g_Vp[VSPLIT * BPRIV * NANCH];
__device__ float g_rz [BPRIV];
__device__ float g_pv [BPRIV];
__device__ float g_rz2[BPRIV];
__device__ float g_scale[BPRIV];

// =====================================================================
// Generic split-K GEMM of the form  out_partial[z] += X * Z^T
// X: [M x kTotal] row-major ld=ldx, Z: [N x kTotal] row-major ld=ldz.
// 128x128 tile, 16-deep k-steps, 8x8 micro-tile, 256 threads,
// register-staged double buffering. Deterministic (no atomics).
// =====================================================================
__global__ void __launch_bounds__(256, 2)
gemm_abt_splitk(const float* __restrict__ X, const float* __restrict__ Z,
                float* __restrict__ partial,
                int M, int N, int ldx, int ldz, int kTotal, int kChunk)
{
    __shared__ __align__(16) float Xs[2][16][132];
    __shared__ __align__(16) float Zs[2][16][132];

    const int tid = threadIdx.x;
    const int bj = blockIdx.x, bi = blockIdx.y, zs = blockIdx.z;
    const int row0 = bi * 128, col0 = bj * 128;
    const int kBeg = zs * kChunk;
    int kEnd = kBeg + kChunk; if (kEnd > kTotal) kEnd = kTotal;
    const int nIter = (kEnd - kBeg + 15) >> 4;

    const int rbase = tid >> 2;          // 0..63
    const int c0    = (tid & 3) << 2;    // 0,4,8,12
    const int tx = tid & 15, ty = tid >> 4;

    float4 sx[2], sz[2];

    auto loadStage = [&](int it) {
        const int kb = kBeg + it * 16;
        const int k  = kb + c0;
        #pragma unroll
        for (int q = 0; q < 2; ++q) {
            const int rr = rbase + q * 64;
            float4 v = make_float4(0.f, 0.f, 0.f, 0.f);
            const int row = row0 + rr;
            if (row < M) {
                const float* p = X + (size_t)row * ldx + k;
                if (k + 4 <= kEnd) v = *(const float4*)p;
                else {
                    float* pv = (float*)&v;
                    for (int e = 0; e < 4; ++e) if (k + e < kEnd) pv[e] = p[e];
                }
            }
            sx[q] = v;
            float4 w = make_float4(0.f, 0.f, 0.f, 0.f);
            const int colr = col0 + rr;
            if (colr < N) {
                const float* p = Z + (size_t)colr * ldz + k;
                if (k + 4 <= kEnd) w = *(const float4*)p;
                else {
                    float* pw = (float*)&w;
                    for (int e = 0; e < 4; ++e) if (k + e < kEnd) pw[e] = p[e];
                }
            }
            sz[q] = w;
        }
    };
    auto storeStage = [&](int buf) {
        #pragma unroll
        for (int q = 0; q < 2; ++q) {
            const int rr = rbase + q * 64;
            Xs[buf][c0+0][rr] = sx[q].x; Xs[buf][c0+1][rr] = sx[q].y;
            Xs[buf][c0+2][rr] = sx[q].z; Xs[buf][c0+3][rr] = sx[q].w;
            Zs[buf][c0+0][rr] = sz[q].x; Zs[buf][c0+1][rr] = sz[q].y;
            Zs[buf][c0+2][rr] = sz[q].z; Zs[buf][c0+3][rr] = sz[q].w;
        }
    };

    float acc[8][8];
    #pragma unroll
    for (int i = 0; i < 8; ++i)
        #pragma unroll
        for (int j = 0; j < 8; ++j) acc[i][j] = 0.f;

    loadStage(0);
    storeStage(0);
    __syncthreads();

    for (int it = 0; it < nIter; ++it) {
        const int buf = it & 1;
        if (it + 1 < nIter) loadStage(it + 1);
        #pragma unroll
        for (int k = 0; k < 16; ++k) {
            float xf[8], zf[8];
            *(float4*)(xf)     = *(const float4*)&Xs[buf][k][ty*8];
            *(float4*)(xf + 4) = *(const float4*)&Xs[buf][k][ty*8 + 4];
            *(float4*)(zf)     = *(const float4*)&Zs[buf][k][tx*8];
            *(float4*)(zf + 4) = *(const float4*)&Zs[buf][k][tx*8 + 4];
            #pragma unroll
            for (int i = 0; i < 8; ++i)
                #pragma unroll
                for (int j = 0; j < 8; ++j)
                    acc[i][j] += xf[i] * zf[j];
        }
        if (it + 1 < nIter) storeStage(buf ^ 1);
        __syncthreads();
    }

    float* dst = partial + (size_t)zs * M * N;
    #pragma unroll
    for (int i = 0; i < 8; ++i) {
        const int row = row0 + ty * 8 + i;
        if (row >= M) continue;
        #pragma unroll
        for (int j = 0; j < 8; ++j) {
            const int col = col0 + tx * 8 + j;
            if (col < N) dst[(size_t)row * N + col] = acc[i][j];
        }
    }
}

// Fixed-order partial reduction (deterministic)
__global__ void reduce_partials(const float* __restrict__ p, float* __restrict__ o,
                                int n, int splits)
{
    const int i = blockIdx.x * 256 + threadIdx.x;
    if (i >= n) return;
    float s = 0.f;
    for (int z = 0; z < splits; ++z) s += p[(size_t)z * n + i];
    o[i] = s;
}

// =====================================================================
// Final GEMM W = Y * A (NN) with fused DP epilogue:
// out = scale_b * W + clamp(priv - W, +-1e-3)
// =====================================================================
__global__ void __launch_bounds__(256, 2)
gemm_nn_epilogue(const float* __restrict__ Y, const float* __restrict__ A,
                 const float* __restrict__ priv, const float* __restrict__ scale,
                 float* __restrict__ out)
{
    const int M = BPRIV, N = PDIM, K = NANCH;
    __shared__ __align__(16) float Xs[2][16][132];
    __shared__ __align__(16) float Bs[2][16][132];

    const int tid = threadIdx.x;
    const int bj = blockIdx.x, bi = blockIdx.y;
    const int row0 = bi * 128, col0 = bj * 128;
    const int nIter = (K + 15) >> 4;    // 63

    const int rbase = tid >> 2;
    const int c0    = (tid & 3) << 2;
    const int tx = tid & 15, ty = tid >> 4;
    const int kk0 = tid >> 5;           // 0..7
    const int j0  = (tid & 31) << 2;    // 0..124

    float4 sx[2], sb[2];

    auto loadStage = [&](int it) {
        const int kb = it * 16;
        {   // X = Y rows (contract along columns)
            const int k = kb + c0;
            #pragma unroll
            for (int q = 0; q < 2; ++q) {
                const int row = row0 + rbase + q * 64;
                float4 v = make_float4(0.f, 0.f, 0.f, 0.f);
                if (row < M) {
                    const float* p = Y + (size_t)row * K + k;
                    if (k + 4 <= K) v = *(const float4*)p;
                    else {
                        float* pv = (float*)&v;
                        for (int e = 0; e < 4; ++e) if (k + e < K) pv[e] = p[e];
                    }
                }
                sx[q] = v;
            }
        }
        {   // B = A[k, p] (k-major, coalesced along p)
            #pragma unroll
            for (int q = 0; q < 2; ++q) {
                const int kk = kk0 + q * 8;
                const int k  = kb + kk;
                const int col = col0 + j0;
                float4 v = make_float4(0.f, 0.f, 0.f, 0.f);
                if (k < K) {
                    const float* p = A + (size_t)k * PDIM + col;
                    if (col + 4 <= N) v = *(const float4*)p;
                    else {
                        float* pv = (float*)&v;
                        for (int e = 0; e < 4; ++e) if (col + e < N) pv[e] = p[e];
                    }
                }
                sb[q] = v;
            }
        }
    };
    auto storeStage = [&](int buf) {
        #pragma unroll
        for (int q = 0; q < 2; ++q) {
            const int rr = rbase + q * 64;
            Xs[buf][c0+0][rr] = sx[q].x; Xs[buf][c0+1][rr] = sx[q].y;
            Xs[buf][c0+2][rr] = sx[q].z; Xs[buf][c0+3][rr] = sx[q].w;
            const int kk = kk0 + q * 8;
            *(float4*)&Bs[buf][kk][j0] = sb[q];
        }
    };

    float acc[8][8];
    #pragma unroll
    for (int i = 0; i < 8; ++i)
        #pragma unroll
        for (int j = 0; j < 8; ++j) acc[i][j] = 0.f;

    loadStage(0);
    storeStage(0);
    __syncthreads();

    for (int it = 0; it < nIter; ++it) {
        const int buf = it & 1;
        if (it + 1 < nIter) loadStage(it + 1);
        #pragma unroll
        for (int k = 0; k < 16; ++k) {
            float xf[8], bf[8];
            *(float4*)(xf)     = *(const float4*)&Xs[buf][k][ty*8];
            *(float4*)(xf + 4) = *(const float4*)&Xs[buf][k][ty*8 + 4];
            *(float4*)(bf)     = *(const float4*)&Bs[buf][k][tx*8];
            *(float4*)(bf + 4) = *(const float4*)&Bs[buf][k][tx*8 + 4];
            #pragma unroll
            for (int i = 0; i < 8; ++i)
                #pragma unroll
                for (int j = 0; j < 8; ++j)
                    acc[i][j] += xf[i] * bf[j];
        }
        if (it + 1 < nIter) storeStage(buf ^ 1);
        __syncthreads();
    }

    // epilogue: out = scale_b * W + clamp(priv - W, +-1e-3)
    #pragma unroll
    for (int i = 0; i < 8; ++i) {
        const int row = row0 + ty * 8 + i;
        if (row >= M) continue;
        const float sc = scale[row];
        #pragma unroll
        for (int jv = 0; jv < 2; ++jv) {
            const int col = col0 + tx * 8 + jv * 4;
            const float* pp = priv + (size_t)row * PDIM + col;
            float*       po = out  + (size_t)row * PDIM + col;
            if (col + 4 <= N) {
                float4 pv = *(const float4*)pp;
                float4 o;
                float* pvf = (float*)&pv; float* of = (float*)&o;
                #pragma unroll
                for (int e = 0; e < 4; ++e) {
                    const float w = acc[i][jv*4 + e];
                    float r = pvf[e] - w;
                    r = fminf(fmaxf(r, -1e-3f), 1e-3f);
                    of[e] = sc * w + r;
                }
                *(float4*)po = o;
            } else {
                for (int e = 0; e < 4; ++e) {
                    if (col + e >= N) break;
                    const float w = acc[i][jv*4 + e];
                    float r = pp[e] - w;
                    r = fminf(fmaxf(r, -1e-3f), 1e-3f);
                    po[e] = sc * w + r;
                }
            }
        }
    }
}

// ------------------- CG helper kernels (one block per RHS row) -------------------
__device__ __forceinline__ float blockReduce256(float v, float* sm)
{
    const int t = threadIdx.x;
    sm[t] = v; __syncthreads();
    #pragma unroll
    for (int s = 128; s > 0; s >>= 1) {
        if (t < s) sm[t] += sm[t + s];
        __syncthreads();
    }
    return sm[0];
}

__global__ void cg_init(const float* __restrict__ C, float* __restrict__ Y,
                        float* __restrict__ Rr, float* __restrict__ Pd,
                        float* __restrict__ rz)
{
    __shared__ float sm[256];
    const int b = blockIdx.x;
    float s = 0.f;
    for (int j = threadIdx.x; j < NANCH; j += 256) {
        const float c = C[b * NANCH + j];
        Y[b * NANCH + j] = 0.f;
        Rr[b * NANCH + j] = c;
        Pd[b * NANCH + j] = c;
        s += c * c;
    }
    const float tot = blockReduce256(s, sm);
    if (threadIdx.x == 0) rz[b] = tot;
}

__global__ void cg_dotpv(const float* __restrict__ Vp, const float* __restrict__ Pd,
                         float* __restrict__ V, float* __restrict__ pv)
{
    __shared__ float sm[256];
    const int b = blockIdx.x;
    float s = 0.f;
    for (int j = threadIdx.x; j < NANCH; j += 256) {
        float v = 0.f;
        #pragma unroll
        for (int z = 0; z < VSPLIT; ++z)
            v += Vp[(size_t)z * BPRIV * NANCH + b * NANCH + j];
        V[b * NANCH + j] = v;
        s += Pd[b * NANCH + j] * v;
    }
    const float tot = blockReduce256(s, sm);
    if (threadIdx.x == 0) pv[b] = tot;
}

__global__ void cg_update(const float* __restrict__ Pd, const float* __restrict__ V,
                          float* __restrict__ Y, float* __restrict__ Rr,
                          const float* __restrict__ rz, const float* __restrict__ pv,
                          float* __restrict__ rz2)
{
    __shared__ float sm[256];
    const int b = blockIdx.x;
    const float pvb = pv[b];
    const float alpha = (pvb > 0.f) ? rz[b] / pvb : 0.f;
    float s = 0.f;
    for (int j = threadIdx.x; j < NANCH; j += 256) {
        Y[b * NANCH + j] += alpha * Pd[b * NANCH + j];
        const float r = Rr[b * NANCH + j] - alpha * V[b * NANCH + j];
        Rr[b * NANCH + j] = r;
        s += r * r;
    }
    const float tot = blockReduce256(s, sm);
    if (threadIdx.x == 0) rz2[b] = tot;
}

__global__ void cg_next(const float* __restrict__ Rr, float* __restrict__ Pd,
                        float* __restrict__ rz, const float* __restrict__ rz2)
{
    const int b = blockIdx.x;
    const float rzb = rz[b];
    const float beta = (rzb > 0.f) ? rz2[b] / rzb : 0.f;
    for (int j = threadIdx.x; j < NANCH; j += 256)
        Pd[b * NANCH + j] = Rr[b * NANCH + j] + beta * Pd[b * NANCH + j];
    if (threadIdx.x == 0) rz[b] = rz2[b];
}

// scale_b = min(1 / ||emb_b||, 1),  ||emb_b||^2 = <Y_b, C_b>
__global__ void scale_kernel(const float* __restrict__ Y, const float* __restrict__ C,
                             float* __restrict__ scale)
{
    __shared__ float sm[256];
    const int b = blockIdx.x;
    float s = 0.f;
    for (int j = threadIdx.x; j < NANCH; j += 256)
        s += Y[b * NANCH + j] * C[b * NANCH + j];
    const float tot = blockReduce256(s, sm);
    if (threadIdx.x == 0) {
        const float n2 = fmaxf(tot, 0.f);
        const float nrm = sqrtf(n2);
        scale[b] = (nrm > 1.0f) ? 1.0f / nrm : 1.0f;
    }
}

// =====================================================================
extern "C" void kernel_launch(void* const* d_in, const int* in_sizes, int n_in,
                              void* d_out, int out_size)
{
    const float* A    = (const float*)d_in[0];   // pub_grad [1000, 100000]
    const float* priv = (const float*)d_in[1];   // priv_grad [256, 100000]
    float* out = (float*)d_out;                  // [256, 100000]

    float *Gp, *G, *Cp, *C, *Y, *Rr, *Pd, *V, *Vp, *rz, *pv, *rz2, *sc;
    cudaGetSymbolAddress((void**)&Gp,  g_Gp);
    cudaGetSymbolAddress((void**)&G,   g_G);
    cudaGetSymbolAddress((void**)&Cp,  g_Cp);
    cudaGetSymbolAddress((void**)&C,   g_C);
    cudaGetSymbolAddress((void**)&Y,   g_Y);
    cudaGetSymbolAddress((void**)&Rr,  g_Rr);
    cudaGetSymbolAddress((void**)&Pd,  g_Pd);
    cudaGetSymbolAddress((void**)&V,   g_V);
    cudaGetSymbolAddress((void**)&Vp,  g_Vp);
    cudaGetSymbolAddress((void**)&rz,  g_rz);
    cudaGetSymbolAddress((void**)&pv,  g_pv);
    cudaGetSymbolAddress((void**)&rz2, g_rz2);
    cudaGetSymbolAddress((void**)&sc,  g_scale);

    const dim3 blk(256);

    // G = A A^T  (1000x1000, contract 100000)
    gemm_abt_splitk<<<dim3(8, 8, GSPLIT), blk>>>(A, A, Gp, NANCH, NANCH,
                                                 PDIM, PDIM, PDIM, PDIM / GSPLIT);
    reduce_partials<<<(NANCH * NANCH + 255) / 256, 256>>>(Gp, G, NANCH * NANCH, GSPLIT);

    // C = priv A^T  (256x1000, contract 100000)
    gemm_abt_splitk<<<dim3(8, 2, CSPLIT), blk>>>(priv, A, Cp, BPRIV, NANCH,
                                                 PDIM, PDIM, PDIM, PDIM / CSPLIT);
    reduce_partials<<<(BPRIV * NANCH + 255) / 256, 256>>>(Cp, C, BPRIV * NANCH, CSPLIT);

    // Batched CG: solve G Y^T = C^T  (256 RHS)
    cg_init<<<BPRIV, 256>>>(C, Y, Rr, Pd, rz);
    for (int it = 0; it < CG_ITERS; ++it) {
        gemm_abt_splitk<<<dim3(8, 2, VSPLIT), blk>>>(Pd, G, Vp, BPRIV, NANCH,
                                                     NANCH, NANCH, NANCH, 128);
        cg_dotpv<<<BPRIV, 256>>>(Vp, Pd, V, pv);
        cg_update<<<BPRIV, 256>>>(Pd, V, Y, Rr, rz, pv, rz2);
        cg_next<<<BPRIV, 256>>>(Rr, Pd, rz, rz2);
    }

    // clip scales + fused decode/residual epilogue
    scale_kernel<<<BPRIV, 256>>>(Y, C, sc);
    gemm_nn_epilogue<<<dim3((PDIM + 127) / 128, 2), blk>>>(Y, A, priv, sc, out);
}

// round 4
// speedup vs baseline: 2.9595x; 2.9595x over previous
#include <cuda_runtime.h>
#include <cuda_bf16.h>
#include <math.h>
#include <stdint.h>

// Problem constants (fixed by dataset)
#define PDIM  100000
#define NANCH 1000
#define BPRIV 256

constexpr int CG_ITERS  = 8;
constexpr int VSPLIT    = 8;      // fp32 CG matvec splits
constexpr int GSPLIT_TC = 4;      // split-K for G
constexpr int GCHUNK    = 25024;  // multiple of 64, 4*25024 >= 100000
constexpr int CSPLIT_TC = 9;      // split-K for C
constexpr int CCHUNK    = 11136;  // multiple of 64, 9*11136 >= 100000

// ---------------- static device scratch (no allocations allowed) ----------------
__device__ __align__(256) __nv_bfloat16 g_Ah [(size_t)NANCH * PDIM];   // 200 MB
__device__ __align__(256) __nv_bfloat16 g_Al [(size_t)NANCH * PDIM];   // 200 MB
__device__ __align__(256) __nv_bfloat16 g_Ath[(size_t)PDIM * NANCH];   // 200 MB
__device__ __align__(256) __nv_bfloat16 g_Atl[(size_t)PDIM * NANCH];   // 200 MB
__device__ __align__(256) __nv_bfloat16 g_Ph [(size_t)BPRIV * PDIM];   // 51 MB
__device__ __align__(256) __nv_bfloat16 g_Pl [(size_t)BPRIV * PDIM];   // 51 MB
__device__ __align__(256) __nv_bfloat16 g_Yh [BPRIV * NANCH];
__device__ __align__(256) __nv_bfloat16 g_Yl [BPRIV * NANCH];
__device__ float g_Gp[GSPLIT_TC * NANCH * NANCH];       // 16 MB
__device__ float g_G [NANCH * NANCH];
__device__ float g_Cp[CSPLIT_TC * BPRIV * NANCH];       // 9.2 MB
__device__ float g_C [BPRIV * NANCH];
__device__ float g_Y [BPRIV * NANCH];
__device__ float g_Rr[BPRIV * NANCH];
__device__ float g_Pd[BPRIV * NANCH];
__device__ float g_V [BPRIV * NANCH];
__device__ float g_Vp[VSPLIT * BPRIV * NANCH];
__device__ float g_rz [BPRIV];
__device__ float g_pv [BPRIV];
__device__ float g_rz2[BPRIV];
__device__ float g_scale[BPRIV];

// ---------------- PTX helpers (plain sm_103-compatible: sm_80+ features) ----------------
__device__ __forceinline__ uint32_t smem_u32(const void* p) {
    uint32_t a;
    asm("{ .reg .u64 t; cvta.to.shared.u64 t, %1; cvt.u32.u64 %0, t; }" : "=r"(a) : "l"(p));
    return a;
}
__device__ __forceinline__ void cp_async16(uint32_t dst, const void* src, int nbytes) {
    asm volatile("cp.async.cg.shared.global [%0], [%1], 16, %2;\n"
                 :: "r"(dst), "l"(src), "r"(nbytes) : "memory");
}
__device__ __forceinline__ void cp_commit() {
    asm volatile("cp.async.commit_group;" ::: "memory");
}
__device__ __forceinline__ void ldsm_x4(uint32_t* r, uint32_t addr) {
    asm volatile("ldmatrix.sync.aligned.m8n8.x4.shared.b16 {%0,%1,%2,%3}, [%4];"
                 : "=r"(r[0]), "=r"(r[1]), "=r"(r[2]), "=r"(r[3]) : "r"(addr));
}
__device__ __forceinline__ void ldsm_x2(uint32_t* r, uint32_t addr) {
    asm volatile("ldmatrix.sync.aligned.m8n8.x2.shared.b16 {%0,%1}, [%2];"
                 : "=r"(r[0]), "=r"(r[1]) : "r"(addr));
}
__device__ __forceinline__ void mma_bf16(float* d, const uint32_t* a, const uint32_t* b) {
    asm volatile("mma.sync.aligned.m16n8k16.row.col.f32.bf16.bf16.f32 "
                 "{%0,%1,%2,%3}, {%4,%5,%6,%7}, {%8,%9}, {%0,%1,%2,%3};"
                 : "+f"(d[0]), "+f"(d[1]), "+f"(d[2]), "+f"(d[3])
                 : "r"(a[0]), "r"(a[1]), "r"(a[2]), "r"(a[3]), "r"(b[0]), "r"(b[1]));
}

// =====================================================================
// Split-bf16 MMA GEMM:  partial[z] = X * Z^T (fp32)
//   X: [M x kTotal] rows (hi/lo), Z: [N x kTotal] rows (hi/lo), common ldK.
//   128x128 CTA tile, k-step 64, 8 warps (64x32 warp tile, m16n8k16),
//   SW128-swizzled smem, 3-stage cp.async pipeline, 3 products hh+hl+lh.
//   Optional fused DP epilogue: out = scale[r]*w + clamp(priv-w, +-1e-3).
// =====================================================================
constexpr int TILE_B  = 128 * 128;        // one 128x64 bf16 tile = 16 KB
constexpr int STAGE_B = 4 * TILE_B;       // Xh,Xl,Zh,Zl = 64 KB
constexpr int NSTAGE  = 3;
constexpr int MMA_SMEM = NSTAGE * STAGE_B; // 192 KB

__global__ void __launch_bounds__(256, 1)
mma_gemm_abt(const __nv_bfloat16* __restrict__ Xh, const __nv_bfloat16* __restrict__ Xl,
             const __nv_bfloat16* __restrict__ Zh, const __nv_bfloat16* __restrict__ Zl,
             float* __restrict__ outp, int M, int N, size_t ldK,
             int kTotal, int kChunk, int lowerTri,
             int epi, const float* __restrict__ priv, const float* __restrict__ scale)
{
    if (lowerTri && blockIdx.x > blockIdx.y) return;
    extern __shared__ char smem[];
    const uint32_t sb = smem_u32(smem);
    const int tid = threadIdx.x, lane = tid & 31, wid = tid >> 5;
    const int wm = wid >> 2, wn = wid & 3;           // 2x4 warp grid
    const int row0 = blockIdx.y * 128, col0 = blockIdx.x * 128;
    const int kBeg = blockIdx.z * kChunk;
    int kEnd = kBeg + kChunk; if (kEnd > kTotal) kEnd = kTotal;
    const int nIter = (kEnd - kBeg + 63) >> 6;

    const __nv_bfloat16* bases[4] = {Xh, Xl, Zh, Zl};

    auto prefetch = [&](int s) {
        const int buf = s % NSTAGE;
        const int kb = kBeg + s * 64;
        #pragma unroll 4
        for (int i = 0; i < 16; ++i) {
            const int slot = i * 256 + tid;          // 0..4095
            const int t    = slot >> 10;             // tile 0..3
            const int w    = slot & 1023;
            const int row  = w >> 3;                 // 0..127
            const int ch   = w & 7;                  // 16B chunk
            const int rglob = ((t < 2) ? row0 : col0) + row;
            const int rmax  = (t < 2) ? M : N;
            const int kg = kb + ch * 8;
            int nb = 0;
            if (rglob < rmax) {
                int av = (kEnd - kg) * 2;
                nb = av < 0 ? 0 : (av > 16 ? 16 : av);
            }
            const __nv_bfloat16* src = (nb > 0) ? bases[t] + (size_t)rglob * ldK + kg
                                                : bases[t];
            const uint32_t dst = sb + (uint32_t)(buf * 4 + t) * (TILE_B)
                               + (uint32_t)(row << 7) + (uint32_t)((ch ^ (row & 7)) << 4);
            cp_async16(dst, src, nb);
        }
        cp_commit();
    };

    float acc[4][4][4];
    #pragma unroll
    for (int mt = 0; mt < 4; ++mt)
        #pragma unroll
        for (int nt = 0; nt < 4; ++nt)
            #pragma unroll
            for (int e = 0; e < 4; ++e) acc[mt][nt][e] = 0.f;

    prefetch(0);
    if (nIter > 1) prefetch(1);

    const int arow  = wm * 64 + (lane & 15);
    const int ahalf = lane >> 4;                    // k-half (0/1) within k16
    const int brow  = wn * 32 + (lane & 7);
    const int bhalf = (lane >> 3) & 1;

    for (int it = 0; it < nIter; ++it) {
        if (it + 1 < nIter) asm volatile("cp.async.wait_group 1;" ::: "memory");
        else                asm volatile("cp.async.wait_group 0;" ::: "memory");
        __syncthreads();
        if (it + 2 < nIter) prefetch(it + 2);

        const uint32_t tb  = sb + (uint32_t)(it % NSTAGE) * STAGE_B;
        const uint32_t tXh = tb, tXl = tb + TILE_B;
        const uint32_t tZh = tb + 2 * TILE_B, tZl = tb + 3 * TILE_B;

        #pragma unroll
        for (int ks = 0; ks < 4; ++ks) {
            uint32_t ah[4][4], al[4][4];
            #pragma unroll
            for (int mt = 0; mt < 4; ++mt) {
                const int r  = arow + mt * 16;
                const int ch = (ks * 2 + ahalf) ^ (r & 7);
                const uint32_t off = (uint32_t)(r << 7) + (uint32_t)(ch << 4);
                ldsm_x4(ah[mt], tXh + off);
                ldsm_x4(al[mt], tXl + off);
            }
            uint32_t bh[4][2], bl[4][2];
            #pragma unroll
            for (int nt = 0; nt < 4; ++nt) {
                const int r  = brow + nt * 8;
                const int ch = (ks * 2 + bhalf) ^ (r & 7);
                const uint32_t off = (uint32_t)(r << 7) + (uint32_t)(ch << 4);
                ldsm_x2(bh[nt], tZh + off);
                ldsm_x2(bl[nt], tZl + off);
            }
            #pragma unroll
            for (int mt = 0; mt < 4; ++mt)
                #pragma unroll
                for (int nt = 0; nt < 4; ++nt) {
                    mma_bf16(acc[mt][nt], ah[mt], bh[nt]);
                    mma_bf16(acc[mt][nt], ah[mt], bl[nt]);
                    mma_bf16(acc[mt][nt], al[mt], bh[nt]);
                }
        }
        __syncthreads();
    }

    // store: d0,d1 -> (r, c..c+1); d2,d3 -> (r+8, c..c+1)
    float* dst = outp + (size_t)blockIdx.z * (size_t)M * N;
    #pragma unroll
    for (int mt = 0; mt < 4; ++mt) {
        const int rA = row0 + wm * 64 + mt * 16 + (lane >> 2);
        #pragma unroll
        for (int nt = 0; nt < 4; ++nt) {
            const int c = col0 + wn * 32 + nt * 8 + (lane & 3) * 2;
            #pragma unroll
            for (int h = 0; h < 2; ++h) {
                const int r = rA + h * 8;
                if (r >= M || c >= N) continue;
                const float v0 = acc[mt][nt][2 * h + 0];
                const float v1 = acc[mt][nt][2 * h + 1];
                float* po = dst + (size_t)r * N + c;
                if (epi) {
                    const float sc = scale[r];
                    const float* pp = priv + (size_t)r * N + c;
                    float r0 = pp[0] - v0; r0 = fminf(fmaxf(r0, -1e-3f), 1e-3f);
                    float r1 = pp[1] - v1; r1 = fminf(fmaxf(r1, -1e-3f), 1e-3f);
                    *(float2*)po = make_float2(sc * v0 + r0, sc * v1 + r1);
                } else {
                    *(float2*)po = make_float2(v0, v1);
                }
            }
        }
    }
}

// ---------------- converts ----------------
__global__ void convA(const float* __restrict__ A,
                      __nv_bfloat16* __restrict__ Ah, __nv_bfloat16* __restrict__ Al,
                      __nv_bfloat16* __restrict__ Ath, __nv_bfloat16* __restrict__ Atl)
{
    __shared__ __nv_bfloat16 sh[32][33];
    __shared__ __nv_bfloat16 sl[32][33];
    const int tx = threadIdx.x, ty = threadIdx.y;
    const int col = blockIdx.x * 32 + tx;      // p
    #pragma unroll
    for (int k = 0; k < 4; ++k) {
        const int row = blockIdx.y * 32 + ty + k * 8;   // n
        float v = 0.f;
        if (row < NANCH) v = A[(size_t)row * PDIM + col];
        const __nv_bfloat16 hb = __float2bfloat16(v);
        const __nv_bfloat16 lb = __float2bfloat16(v - __bfloat162float(hb));
        if (row < NANCH) {
            Ah[(size_t)row * PDIM + col] = hb;
            Al[(size_t)row * PDIM + col] = lb;
        }
        sh[ty + k * 8][tx] = hb;
        sl[ty + k * 8][tx] = lb;
    }
    __syncthreads();
    #pragma unroll
    for (int k = 0; k < 4; ++k) {
        const int p = blockIdx.x * 32 + ty + k * 8;
        const int n = blockIdx.y * 32 + tx;
        if (n < NANCH) {
            Ath[(size_t)p * NANCH + n] = sh[tx][ty + k * 8];
            Atl[(size_t)p * NANCH + n] = sl[tx][ty + k * 8];
        }
    }
}

__global__ void convSplit(const float* __restrict__ X,
                          __nv_bfloat16* __restrict__ H, __nv_bfloat16* __restrict__ L,
                          size_t n)
{
    const size_t stride = (size_t)gridDim.x * blockDim.x;
    for (size_t i = (size_t)blockIdx.x * blockDim.x + threadIdx.x; i < n; i += stride) {
        const float v = X[i];
        const __nv_bfloat16 hb = __float2bfloat16(v);
        H[i] = hb;
        L[i] = __float2bfloat16(v - __bfloat162float(hb));
    }
}

// ---------------- small helpers ----------------
__global__ void reduce_partials(const float* __restrict__ p, float* __restrict__ o,
                                int n, int splits)
{
    const int i = blockIdx.x * 256 + threadIdx.x;
    if (i >= n) return;
    float s = 0.f;
    for (int z = 0; z < splits; ++z) s += p[(size_t)z * n + i];
    o[i] = s;
}

__global__ void mirrorG(float* __restrict__ G)
{
    const int idx = blockIdx.x * 256 + threadIdx.x;
    if (idx >= NANCH * NANCH) return;
    const int i = idx / NANCH, j = idx - i * NANCH;
    if (j > i) G[idx] = G[j * NANCH + i];
}

// =====================================================================
// fp32 SIMT split-K GEMM (used only for CG matvec, K=1000 — tiny)
// =====================================================================
__global__ void __launch_bounds__(256, 2)
gemm_abt_splitk(const float* __restrict__ X, const float* __restrict__ Z,
                float* __restrict__ partial,
                int M, int N, int ldx, int ldz, int kTotal, int kChunk)
{
    __shared__ __align__(16) float Xs[2][16][132];
    __shared__ __align__(16) float Zs[2][16][132];

    const int tid = threadIdx.x;
    const int bj = blockIdx.x, bi = blockIdx.y, zs = blockIdx.z;
    const int row0 = bi * 128, col0 = bj * 128;
    const int kBeg = zs * kChunk;
    int kEnd = kBeg + kChunk; if (kEnd > kTotal) kEnd = kTotal;
    const int nIter = (kEnd - kBeg + 15) >> 4;

    const int rbase = tid >> 2;
    const int c0    = (tid & 3) << 2;
    const int tx = tid & 15, ty = tid >> 4;

    float4 sx[2], sz[2];

    auto loadStage = [&](int it) {
        const int kb = kBeg + it * 16;
        const int k  = kb + c0;
        #pragma unroll
        for (int q = 0; q < 2; ++q) {
            const int rr = rbase + q * 64;
            float4 v = make_float4(0.f, 0.f, 0.f, 0.f);
            const int row = row0 + rr;
            if (row < M) {
                const float* p = X + (size_t)row * ldx + k;
                if (k + 4 <= kEnd) v = *(const float4*)p;
                else { float* pv = (float*)&v; for (int e = 0; e < 4; ++e) if (k + e < kEnd) pv[e] = p[e]; }
            }
            sx[q] = v;
            float4 w = make_float4(0.f, 0.f, 0.f, 0.f);
            const int colr = col0 + rr;
            if (colr < N) {
                const float* p = Z + (size_t)colr * ldz + k;
                if (k + 4 <= kEnd) w = *(const float4*)p;
                else { float* pw = (float*)&w; for (int e = 0; e < 4; ++e) if (k + e < kEnd) pw[e] = p[e]; }
            }
            sz[q] = w;
        }
    };
    auto storeStage = [&](int buf) {
        #pragma unroll
        for (int q = 0; q < 2; ++q) {
            const int rr = rbase + q * 64;
            Xs[buf][c0+0][rr] = sx[q].x; Xs[buf][c0+1][rr] = sx[q].y;
            Xs[buf][c0+2][rr] = sx[q].z; Xs[buf][c0+3][rr] = sx[q].w;
            Zs[buf][c0+0][rr] = sz[q].x; Zs[buf][c0+1][rr] = sz[q].y;
            Zs[buf][c0+2][rr] = sz[q].z; Zs[buf][c0+3][rr] = sz[q].w;
        }
    };

    float acc[8][8];
    #pragma unroll
    for (int i = 0; i < 8; ++i)
        #pragma unroll
        for (int j = 0; j < 8; ++j) acc[i][j] = 0.f;

    loadStage(0); storeStage(0); __syncthreads();

    for (int it = 0; it < nIter; ++it) {
        const int buf = it & 1;
        if (it + 1 < nIter) loadStage(it + 1);
        #pragma unroll
        for (int k = 0; k < 16; ++k) {
            float xf[8], zf[8];
            *(float4*)(xf)     = *(const float4*)&Xs[buf][k][ty*8];
            *(float4*)(xf + 4) = *(const float4*)&Xs[buf][k][ty*8 + 4];
            *(float4*)(zf)     = *(const float4*)&Zs[buf][k][tx*8];
            *(float4*)(zf + 4) = *(const float4*)&Zs[buf][k][tx*8 + 4];
            #pragma unroll
            for (int i = 0; i < 8; ++i)
                #pragma unroll
                for (int j = 0; j < 8; ++j)
                    acc[i][j] += xf[i] * zf[j];
        }
        if (it + 1 < nIter) storeStage(buf ^ 1);
        __syncthreads();
    }

    float* dst = partial + (size_t)zs * M * N;
    #pragma unroll
    for (int i = 0; i < 8; ++i) {
        const int row = row0 + ty * 8 + i;
        if (row >= M) continue;
        #pragma unroll
        for (int j = 0; j < 8; ++j) {
            const int col = col0 + tx * 8 + j;
            if (col < N) dst[(size_t)row * N + col] = acc[i][j];
        }
    }
}

// ---------------- CG kernels ----------------
__device__ __forceinline__ float blockReduce256(float v, float* sm)
{
    const int t = threadIdx.x;
    sm[t] = v; __syncthreads();
    #pragma unroll
    for (int s = 128; s > 0; s >>= 1) {
        if (t < s) sm[t] += sm[t + s];
        __syncthreads();
    }
    return sm[0];
}

__global__ void cg_init(const float* __restrict__ C, float* __restrict__ Y,
                        float* __restrict__ Rr, float* __restrict__ Pd,
                        float* __restrict__ rz)
{
    __shared__ float sm[256];
    const int b = blockIdx.x;
    float s = 0.f;
    for (int j = threadIdx.x; j < NANCH; j += 256) {
        const float c = C[b * NANCH + j];
        Y[b * NANCH + j] = 0.f;
        Rr[b * NANCH + j] = c;
        Pd[b * NANCH + j] = c;
        s += c * c;
    }
    const float tot = blockReduce256(s, sm);
    if (threadIdx.x == 0) rz[b] = tot;
}

__global__ void cg_dotpv(const float* __restrict__ Vp, const float* __restrict__ Pd,
                         float* __restrict__ V, float* __restrict__ pv)
{
    __shared__ float sm[256];
    const int b = blockIdx.x;
    float s = 0.f;
    for (int j = threadIdx.x; j < NANCH; j += 256) {
        float v = 0.f;
        #pragma unroll
        for (int z = 0; z < VSPLIT; ++z)
            v += Vp[(size_t)z * BPRIV * NANCH + b * NANCH + j];
        V[b * NANCH + j] = v;
        s += Pd[b * NANCH + j] * v;
    }
    const float tot = blockReduce256(s, sm);
    if (threadIdx.x == 0) pv[b] = tot;
}

__global__ void cg_update(const float* __restrict__ Pd, const float* __restrict__ V,
                          float* __restrict__ Y, float* __restrict__ Rr,
                          const float* __restrict__ rz, const float* __restrict__ pv,
                          float* __restrict__ rz2)
{
    __shared__ float sm[256];
    const int b = blockIdx.x;
    const float pvb = pv[b];
    const float alpha = (pvb > 0.f) ? rz[b] / pvb : 0.f;
    float s = 0.f;
    for (int j = threadIdx.x; j < NANCH; j += 256) {
        Y[b * NANCH + j] += alpha * Pd[b * NANCH + j];
        const float r = Rr[b * NANCH + j] - alpha * V[b * NANCH + j];
        Rr[b * NANCH + j] = r;
        s += r * r;
    }
    const float tot = blockReduce256(s, sm);
    if (threadIdx.x == 0) rz2[b] = tot;
}

__global__ void cg_next(const float* __restrict__ Rr, float* __restrict__ Pd,
                        float* __restrict__ rz, const float* __restrict__ rz2)
{
    const int b = blockIdx.x;
    const float rzb = rz[b];
    const float beta = (rzb > 0.f) ? rz2[b] / rzb : 0.f;
    for (int j = threadIdx.x; j < NANCH; j += 256)
        Pd[b * NANCH + j] = Rr[b * NANCH + j] + beta * Pd[b * NANCH + j];
    if (threadIdx.x == 0) rz[b] = rz2[b];
}

__global__ void scale_kernel(const float* __restrict__ Y, const float* __restrict__ C,
                             float* __restrict__ scale)
{
    __shared__ float sm[256];
    const int b = blockIdx.x;
    float s = 0.f;
    for (int j = threadIdx.x; j < NANCH; j += 256)
        s += Y[b * NANCH + j] * C[b * NANCH + j];
    const float tot = blockReduce256(s, sm);
    if (threadIdx.x == 0) {
        const float n2 = fmaxf(tot, 0.f);
        const float nrm = sqrtf(n2);
        scale[b] = (nrm > 1.0f) ? 1.0f / nrm : 1.0f;
    }
}

// =====================================================================
extern "C" void kernel_launch(void* const* d_in, const int* in_sizes, int n_in,
                              void* d_out, int out_size)
{
    const float* A    = (const float*)d_in[0];   // pub_grad [1000, 100000]
    const float* priv = (const float*)d_in[1];   // priv_grad [256, 100000]
    float* out = (float*)d_out;                  // [256, 100000]

    __nv_bfloat16 *Ah, *Al, *Ath, *Atl, *Ph, *Pl, *Yh, *Yl;
    float *Gp, *G, *Cp, *C, *Y, *Rr, *Pd, *V, *Vp, *rz, *pv, *rz2, *sc;
    cudaGetSymbolAddress((void**)&Ah,  g_Ah);
    cudaGetSymbolAddress((void**)&Al,  g_Al);
    cudaGetSymbolAddress((void**)&Ath, g_Ath);
    cudaGetSymbolAddress((void**)&Atl, g_Atl);
    cudaGetSymbolAddress((void**)&Ph,  g_Ph);
    cudaGetSymbolAddress((void**)&Pl,  g_Pl);
    cudaGetSymbolAddress((void**)&Yh,  g_Yh);
    cudaGetSymbolAddress((void**)&Yl,  g_Yl);
    cudaGetSymbolAddress((void**)&Gp,  g_Gp);
    cudaGetSymbolAddress((void**)&G,   g_G);
    cudaGetSymbolAddress((void**)&Cp,  g_Cp);
    cudaGetSymbolAddress((void**)&C,   g_C);
    cudaGetSymbolAddress((void**)&Y,   g_Y);
    cudaGetSymbolAddress((void**)&Rr,  g_Rr);
    cudaGetSymbolAddress((void**)&Pd,  g_Pd);
    cudaGetSymbolAddress((void**)&V,   g_V);
    cudaGetSymbolAddress((void**)&Vp,  g_Vp);
    cudaGetSymbolAddress((void**)&rz,  g_rz);
    cudaGetSymbolAddress((void**)&pv,  g_pv);
    cudaGetSymbolAddress((void**)&rz2, g_rz2);
    cudaGetSymbolAddress((void**)&sc,  g_scale);

    static bool attrDone = false;
    cudaFuncSetAttribute(mma_gemm_abt, cudaFuncAttributeMaxDynamicSharedMemorySize, MMA_SMEM);
    (void)attrDone;

    // 1) split A into bf16 hi/lo + transposed copies
    convA<<<dim3(PDIM / 32, (NANCH + 31) / 32), dim3(32, 8)>>>(A, Ah, Al, Ath, Atl);
    // 2) split priv
    convSplit<<<480, 256>>>(priv, Ph, Pl, (size_t)BPRIV * PDIM);

    // 3) G = A A^T  (mma, lower triangle + mirror)
    mma_gemm_abt<<<dim3(8, 8, GSPLIT_TC), 256, MMA_SMEM>>>(
        Ah, Al, Ah, Al, Gp, NANCH, NANCH, (size_t)PDIM, PDIM, GCHUNK, 1,
        0, nullptr, nullptr);
    reduce_partials<<<(NANCH * NANCH + 255) / 256, 256>>>(Gp, G, NANCH * NANCH, GSPLIT_TC);
    mirrorG<<<(NANCH * NANCH + 255) / 256, 256>>>(G);

    // 4) C = priv A^T (mma)
    mma_gemm_abt<<<dim3(8, 2, CSPLIT_TC), 256, MMA_SMEM>>>(
        Ph, Pl, Ah, Al, Cp, BPRIV, NANCH, (size_t)PDIM, PDIM, CCHUNK, 0,
        0, nullptr, nullptr);
    reduce_partials<<<(BPRIV * NANCH + 255) / 256, 256>>>(Cp, C, BPRIV * NANCH, CSPLIT_TC);

    // 5) Batched CG: G Y^T = C^T (256 RHS), fp32
    cg_init<<<BPRIV, 256>>>(C, Y, Rr, Pd, rz);
    for (int it = 0; it < CG_ITERS; ++it) {
        gemm_abt_splitk<<<dim3(8, 2, VSPLIT), 256>>>(Pd, G, Vp, BPRIV, NANCH,
                                                     NANCH, NANCH, NANCH, 128);
        cg_dotpv<<<BPRIV, 256>>>(Vp, Pd, V, pv);
        cg_update<<<BPRIV, 256>>>(Pd, V, Y, Rr, rz, pv, rz2);
        cg_next<<<BPRIV, 256>>>(Rr, Pd, rz, rz2);
    }

    // 6) clip scale + split Y
    scale_kernel<<<BPRIV, 256>>>(Y, C, sc);
    convSplit<<<64, 256>>>(Y, Yh, Yl, (size_t)BPRIV * NANCH);

    // 7) W = Y * A with fused DP epilogue, written directly to out
    mma_gemm_abt<<<dim3((PDIM + 127) / 128, 2, 1), 256, MMA_SMEM>>>(
        Yh, Yl, Ath, Atl, out, BPRIV, PDIM, (size_t)NANCH, NANCH, NANCH, 0,
        1, priv, sc);
}